// round 3
// baseline (speedup 1.0000x reference)
#include <cuda_runtime.h>
#include <stdint.h>

#define N_NODES 50000
#define N_EDGES 800000
#define IN_F    256
#define OUT_F   64

typedef unsigned long long ull;

// Scratch for h = x @ W  (50000 x 64 fp32 = 12.8 MB) — device global (no allocs allowed)
__device__ float g_h[N_NODES * OUT_F];

// ---------------------------------------------------------------------------
// Kernel 1: h = x @ W  as register-blocked SGEMM with packed fma.rn.f32x2.
//   M = 50000, N = 64, K = 256
//   BM=128 x BN=64, BK=16. 128 threads, each owns an 8x8 tile.
//   Accumulators packed as f32x2 over row pairs; a-pairs load directly from
//   shared via ld.shared.v2.b64 (no pack); b broadcast packed via mov.b64.
// ---------------------------------------------------------------------------
#define BM 128
#define BN 64
#define BK 16
#define XS_STRIDE (BM + 4)     // 132; row = 528 B, keeps 16B alignment

__global__ void __launch_bounds__(128, 4) gemm_kernel(
    const float* __restrict__ x, const float* __restrict__ w)
{
    __shared__ __align__(16) float xs[2][BK][XS_STRIDE];  // x tile, transposed: xs[k][m]
    __shared__ __align__(16) float ws[2][BK][BN];         // w tile: ws[k][n]

    const int tid = threadIdx.x;
    const int tx = tid & 7;           // n0 = tx*8
    const int ty = tid >> 3;          // m0 = ty*8
    const int m0 = ty * 8, n0 = tx * 8;
    const int block_m = blockIdx.x * BM;

    // ---- x-tile loader: 128x16 floats = 512 float4; 4 float4 per thread ----
    const int xrow = tid >> 2;              // 0..31
    const int xkc  = (tid & 3) << 2;        // 0,4,8,12
    const float* xp[4];
    #pragma unroll
    for (int q = 0; q < 4; q++) {
        int r = min(block_m + xrow + 32 * q, N_NODES - 1);  // clamp; store guarded
        xp[q] = x + (size_t)r * IN_F + xkc;
    }

    // ---- w-tile loader: 16x64 floats = 256 float4; 2 float4 per thread ----
    const int widx0 = tid * 2;

    float4 xf[4];
    float4 wf[2];
    #pragma unroll
    for (int q = 0; q < 4; q++) xf[q] = *(const float4*)xp[q];
    #pragma unroll
    for (int p = 0; p < 2; p++) {
        const int idx = widx0 + p;
        wf[p] = *(const float4*)(w + (size_t)(idx >> 4) * OUT_F + (idx & 15) * 4);
    }

    ull acc[4][8];
    #pragma unroll
    for (int i = 0; i < 4; i++)
        #pragma unroll
        for (int j = 0; j < 8; j++) acc[i][j] = 0ull;

    // stage tile 0 into buffer 0
    #pragma unroll
    for (int q = 0; q < 4; q++) {
        xs[0][xkc + 0][xrow + 32 * q] = xf[q].x;
        xs[0][xkc + 1][xrow + 32 * q] = xf[q].y;
        xs[0][xkc + 2][xrow + 32 * q] = xf[q].z;
        xs[0][xkc + 3][xrow + 32 * q] = xf[q].w;
    }
    #pragma unroll
    for (int p = 0; p < 2; p++) {
        const int idx = widx0 + p;
        *(float4*)&ws[0][idx >> 4][(idx & 15) * 4] = wf[p];
    }
    __syncthreads();

    const int NKT = IN_F / BK;   // 16 k-tiles

    #pragma unroll 1
    for (int kt = 0; kt < NKT; kt++) {
        const int buf = kt & 1;

        // prefetch next tile global -> registers
        if (kt + 1 < NKT) {
            const int k0 = (kt + 1) * BK;
            #pragma unroll
            for (int q = 0; q < 4; q++) xf[q] = *(const float4*)(xp[q] + k0);
            #pragma unroll
            for (int p = 0; p < 2; p++) {
                const int idx = widx0 + p;
                wf[p] = *(const float4*)(w + (size_t)(k0 + (idx >> 4)) * OUT_F + (idx & 15) * 4);
            }
        }

        // compute on current buffer
        #pragma unroll
        for (int k = 0; k < BK; k++) {
            // a-row pairs, loaded pre-packed (rows m0+0/1, +2/3, +4/5, +6/7)
            const double2 av0 = *(const double2*)&xs[buf][k][m0];
            const double2 av1 = *(const double2*)&xs[buf][k][m0 + 4];
            ull a2[4];
            a2[0] = __double_as_longlong(av0.x);
            a2[1] = __double_as_longlong(av0.y);
            a2[2] = __double_as_longlong(av1.x);
            a2[3] = __double_as_longlong(av1.y);

            const float4 b0 = *(const float4*)&ws[buf][k][n0];
            const float4 b1 = *(const float4*)&ws[buf][k][n0 + 4];
            const float bs[8] = {b0.x, b0.y, b0.z, b0.w, b1.x, b1.y, b1.z, b1.w};

            #pragma unroll
            for (int j = 0; j < 8; j++) {
                ull bb;
                const unsigned bu = __float_as_uint(bs[j]);
                asm("mov.b64 %0, {%1, %1};" : "=l"(bb) : "r"(bu));
                #pragma unroll
                for (int i = 0; i < 4; i++)
                    asm("fma.rn.f32x2 %0, %1, %2, %0;"
                        : "+l"(acc[i][j]) : "l"(a2[i]), "l"(bb));
            }
        }

        // stage prefetched tile into other buffer (safe: it was last read in kt-1,
        // and the sync at the end of kt-1 ordered that), then one sync.
        if (kt + 1 < NKT) {
            const int nb = buf ^ 1;
            #pragma unroll
            for (int q = 0; q < 4; q++) {
                xs[nb][xkc + 0][xrow + 32 * q] = xf[q].x;
                xs[nb][xkc + 1][xrow + 32 * q] = xf[q].y;
                xs[nb][xkc + 2][xrow + 32 * q] = xf[q].z;
                xs[nb][xkc + 3][xrow + 32 * q] = xf[q].w;
            }
            #pragma unroll
            for (int p = 0; p < 2; p++) {
                const int idx = widx0 + p;
                *(float4*)&ws[nb][idx >> 4][(idx & 15) * 4] = wf[p];
            }
            __syncthreads();
        }
    }

    // ---- epilogue: unpack row pairs and store 8x8 tile ----
    #pragma unroll
    for (int i = 0; i < 4; i++) {
        float lo[8], hi[8];
        #pragma unroll
        for (int j = 0; j < 8; j++) {
            unsigned ulo, uhi;
            asm("mov.b64 {%0, %1}, %2;" : "=r"(ulo), "=r"(uhi) : "l"(acc[i][j]));
            lo[j] = __uint_as_float(ulo);
            hi[j] = __uint_as_float(uhi);
        }
        const int r0 = block_m + m0 + 2 * i;
        if (r0 < N_NODES) {
            *(float4*)(g_h + (size_t)r0 * OUT_F + n0)     = make_float4(lo[0], lo[1], lo[2], lo[3]);
            *(float4*)(g_h + (size_t)r0 * OUT_F + n0 + 4) = make_float4(lo[4], lo[5], lo[6], lo[7]);
        }
        if (r0 + 1 < N_NODES) {
            *(float4*)(g_h + (size_t)(r0 + 1) * OUT_F + n0)     = make_float4(hi[0], hi[1], hi[2], hi[3]);
            *(float4*)(g_h + (size_t)(r0 + 1) * OUT_F + n0 + 4) = make_float4(hi[4], hi[5], hi[6], hi[7]);
        }
    }
}

// ---------------------------------------------------------------------------
// Kernel 2: out[n][f] = bias[f]   (out is poisoned; must init before atomics)
// ---------------------------------------------------------------------------
__global__ void init_kernel(float* __restrict__ out, const float* __restrict__ bias)
{
    const int t = blockIdx.x * blockDim.x + threadIdx.x;
    const int total4 = N_NODES * OUT_F / 4;
    if (t < total4) {
        const float4* b4 = (const float4*)bias;
        ((float4*)out)[t] = __ldg(&b4[t & 15]);
    }
}

// ---------------------------------------------------------------------------
// Kernel 3: scatter — out[dst] += w_e * h[src].  16 threads per edge,
// each thread does one float4 slice via red.global.add.v4.f32 (sm_90+).
// ---------------------------------------------------------------------------
__global__ void scatter_kernel(const float* __restrict__ ew,
                               const int* __restrict__ esrc,
                               const int* __restrict__ edst,
                               float* __restrict__ out)
{
    const int t = blockIdx.x * blockDim.x + threadIdx.x;
    const int e = t >> 4;
    if (e >= N_EDGES) return;
    const int c = (t & 15) << 2;

    const int src = __ldg(&esrc[e]);
    const int dst = __ldg(&edst[e]);
    const float w = __ldg(&ew[e]);

    const float4 hv = *(const float4*)(g_h + (size_t)src * OUT_F + c);
    float* p = out + (size_t)dst * OUT_F + c;
    asm volatile("red.global.add.v4.f32 [%0], {%1, %2, %3, %4};"
                 :: "l"(p), "f"(hv.x * w), "f"(hv.y * w), "f"(hv.z * w), "f"(hv.w * w)
                 : "memory");
}

// ---------------------------------------------------------------------------
// inputs (metadata order): x, weight, bias, edge_weight, edge_src, edge_dst
// ---------------------------------------------------------------------------
extern "C" void kernel_launch(void* const* d_in, const int* in_sizes, int n_in,
                              void* d_out, int out_size)
{
    const float* x      = (const float*)d_in[0];
    const float* weight = (const float*)d_in[1];
    const float* bias   = (const float*)d_in[2];
    const float* ew     = (const float*)d_in[3];
    const int*   esrc   = (const int*)d_in[4];
    const int*   edst   = (const int*)d_in[5];
    float* out = (float*)d_out;

    // 1) h = x @ W   (FFMA2 register-blocked SGEMM)
    {
        const int grid = (N_NODES + BM - 1) / BM;   // 391
        gemm_kernel<<<grid, 128>>>(x, weight);
    }

    // 2) out = bias
    {
        const int total4 = N_NODES * OUT_F / 4;
        init_kernel<<<(total4 + 255) / 256, 256>>>(out, bias);
    }

    // 3) scatter-add over edges
    {
        const long long threads = (long long)N_EDGES * 16;
        const int blk = 256;
        const int grid = (int)((threads + blk - 1) / blk);
        scatter_kernel<<<grid, blk>>>(ew, esrc, edst, out);
    }
}